// round 13
// baseline (speedup 1.0000x reference)
#include <cuda_runtime.h>
#include <cstdint>

// Problem constants (from reference): V=100000 vocab, D=128 dim, R=20000
#define VOCAB 100000
#define DIM4  32   // 128 floats = 32 float4
#define RES_BIT (1u << 30)
#define TPW   8    // tokens per warp
#define BATCH 4    // tokens per copy stage (independent LDG.128 in flight)

// Single fused kernel: no scatter pass, no remap table, no second launch.
// Phase 1: each lane resolves token (lane & 7) via a branchless lower_bound
//          binary search over the sorted residual_index (80 KB, L2-resident;
//          the top ~10 tree levels live in L1 since every warp probes the
//          same few lines). 15 fixed iterations, no divergence.
// Phase 2: copy loop, BATCH tokens per stage, each lane moves one float4
//          per token. Streaming stores keep the tables L2-resident.
// __launch_bounds__(256, 8) pins regs <= 32 so 8 CTAs reside per SM.
__global__ __launch_bounds__(256, 8)
void fused_gather_kernel(const int* __restrict__ x,
                         const int* __restrict__ ridx,     // [R] sorted
                         const float4* __restrict__ pre,   // [V, 32] float4
                         const float4* __restrict__ res,   // [R, 32] float4
                         float4* __restrict__ out,         // [n_tok, 32] float4
                         int n_tok, int R) {
    int warp = (blockIdx.x * blockDim.x + threadIdx.x) >> 5;
    int lane = threadIdx.x & 31;
    long long base = (long long)warp * TPW;
    if (base >= n_tok) return;
    bool full = (base + TPW <= n_tok);

    // ---- Phase 1: branchless lower_bound per lane ----
    long long mytok = base + (lane & (TPW - 1));
    int v = (mytok < n_tok) ? __ldg(x + mytok) : 0;

    int pos = 0;
    #pragma unroll
    for (int step = 16384; step > 0; step >>= 1) {
        int probe = pos + step;
        if (probe <= R && __ldg(ridx + probe - 1) < v)
            pos = probe;
    }
    // pos = lower_bound(ridx, v); residual iff exact match
    bool use_res = (pos < R) && (__ldg(ridx + pos) == v);
    // pack: bit30 = residual flag, low bits = row index (fits: V < 2^17)
    unsigned packed = use_res ? ((unsigned)pos | RES_BIT) : (unsigned)v;

    if (full) {
        // Fast path: no bounds checks, BATCH-deep load pipelining.
        #pragma unroll
        for (int t0 = 0; t0 < TPW; t0 += BATCH) {
            float4 val[BATCH];
            #pragma unroll
            for (int k = 0; k < BATCH; k++) {
                unsigned p = __shfl_sync(0xFFFFFFFFu, packed, t0 + k);
                const float4* srow = (p & RES_BIT)
                                   ? (res + (long long)(p & ~RES_BIT) * DIM4)
                                   : (pre + (long long)p * DIM4);
                val[k] = __ldg(srow + lane);
            }
            #pragma unroll
            for (int k = 0; k < BATCH; k++)
                __stcs(out + (base + t0 + k) * DIM4 + lane, val[k]);
        }
    } else {
        // Tail warp (not hit for n_tok % TPW == 0, kept for generality).
        for (int t = 0; t < TPW; t++) {
            long long tok = base + t;
            if (tok >= n_tok) break;
            unsigned p = __shfl_sync(0xFFFFFFFFu, packed, t);
            const float4* srow = (p & RES_BIT)
                               ? (res + (long long)(p & ~RES_BIT) * DIM4)
                               : (pre + (long long)p * DIM4);
            __stcs(out + tok * DIM4 + lane, __ldg(srow + lane));
        }
    }
}

extern "C" void kernel_launch(void* const* d_in, const int* in_sizes, int n_in,
                              void* d_out, int out_size) {
    // Input order per reference setup_inputs():
    //   0: x                    [B*S]   int32
    //   1: residual_index       [R]     int32
    //   2: pretrained_embedding [V*D]   float32
    //   3: residual_embedding   [R*D]   float32
    const int*    x    = (const int*)d_in[0];
    const int*    ridx = (const int*)d_in[1];
    const float4* pre  = (const float4*)d_in[2];
    const float4* res  = (const float4*)d_in[3];
    float4*       out  = (float4*)d_out;

    const int n_tok = in_sizes[0];          // B*S = 262144
    const int R     = in_sizes[1];          // 20000

    const long long n_warps = ((long long)n_tok + TPW - 1) / TPW;
    const long long total_threads = n_warps * 32;
    const int block = 256;
    const int grid  = (int)((total_threads + block - 1) / block);
    fused_gather_kernel<<<grid, block>>>(x, ridx, pre, res, out, n_tok, R);
}